// round 12
// baseline (speedup 1.0000x reference)
#include <cuda_runtime.h>
#include <cstdint>

#define GW      1024
#define GH      1024
#define W_OUT   4096
#define H_OUT   4096
#define NCH     4
#define GPLANE  (GH * GW)          // 1048576
#define OPLANE  (H_OUT * W_OUT)    // 16777216
#define TILE    1024               // period of the output in both axes

// L2 evict_last access policy (created once per thread, uniform).
__device__ __forceinline__ uint64_t make_evict_last_policy() {
    uint64_t pol;
    asm("createpolicy.fractional.L2::evict_last.b64 %0, 1.0;" : "=l"(pol));
    return pol;
}

// Read-only global load carrying the evict_last L2 cache hint: protects the
// 16MB grid from being flushed out of L2 by the 256MB output write stream.
__device__ __forceinline__ float ldg_hint(const float* p, uint64_t pol) {
    float v;
    asm("ld.global.nc.L2::cache_hint.f32 %0, [%1], %2;"
        : "=f"(v) : "l"(p), "l"(pol));
    return v;
}

// Faithful fp32 replication of the reference coordinate chain:
//   f = (v - 511.5)/511.5 ; t = ((f + 1) * 0.5) * 1023 ; clip ; floor
__device__ __forceinline__ void axis_entry(int v, int* p0, float* pw) {
    float fv = __fadd_rn((float)v, -511.5f);
    float f  = __fdiv_rn(fv, 511.5f);
    float t  = __fmul_rn(__fmul_rn(__fadd_rn(f, 1.0f), 0.5f), 1023.0f);
    t = fminf(fmaxf(t, 0.0f), 1023.0f);
    float f0 = floorf(t);
    *p0 = (int)f0;
    *pw = __fadd_rn(t, -f0);
}

// One thread per UNIQUE pixel (1024x1024), 4096 CTAs x 256 threads.
// 16 evict_last L2 gathers + 4-channel bilinear, then 64 plain coalesced
// scalar stores (16 periodic replicas x 4 channels).
__global__ void __launch_bounds__(256) sample_rep_el_kernel(const float* __restrict__ grid,
                                                            const int* __restrict__ cs,
                                                            float* __restrict__ out) {
    const int t = blockIdx.x * blockDim.x + threadIdx.x;   // 0 .. 1048575
    const int x = t & (TILE - 1);
    const int y = t >> 10;

    const int cs0 = cs[0];
    const int cs1 = cs[1];

    int x0; float wx;
    axis_entry((cs0 + x) & (GW - 1), &x0, &wx);
    int y0; float wy;
    axis_entry((cs1 + y) & (GH - 1), &y0, &wy);   // warp-uniform

    const int   x1  = min(x0 + 1, GW - 1);
    const int   y1  = min(y0 + 1, GH - 1);
    const float omx = 1.0f - wx;
    const float omy = 1.0f - wy;

    const uint64_t pol = make_evict_last_policy();

    const float* r0 = grid + y0 * GW;
    const float* r1 = grid + y1 * GW;

    float v[NCH];
#pragma unroll
    for (int c = 0; c < NCH; ++c) {
        const float* p0 = r0 + c * GPLANE;
        const float* p1 = r1 + c * GPLANE;
        float v00 = ldg_hint(p0 + x0, pol);
        float v01 = ldg_hint(p0 + x1, pol);
        float v10 = ldg_hint(p1 + x0, pol);
        float v11 = ldg_hint(p1 + x1, pol);
        float top = v00 * omx + v01 * wx;
        float bot = v10 * omx + v11 * wx;
        v[c] = top * omy + bot * wy;
    }

    const int obase = y * W_OUT + x;
#pragma unroll
    for (int c = 0; c < NCH; ++c) {
        float* po = out + c * OPLANE + obase;
        const float val = v[c];
#pragma unroll
        for (int dy = 0; dy < 4; ++dy) {
#pragma unroll
            for (int dx = 0; dx < 4; ++dx) {
                po[dy * (TILE * W_OUT) + dx * TILE] = val;
            }
        }
    }
}

extern "C" void kernel_launch(void* const* d_in, const int* in_sizes, int n_in,
                              void* d_out, int out_size) {
    const float* grid = (const float*)d_in[0];
    const int*   cs   = (const int*)d_in[1];
    float*       out  = (float*)d_out;

    sample_rep_el_kernel<<<(TILE * TILE) / 256, 256>>>(grid, cs, out);
}